// round 15
// baseline (speedup 1.0000x reference)
#include <cuda_runtime.h>
#include <cstdint>

// out_half[h] = X[idx[h], :]  (512B per half-row), h in [0, 2E)
// Stage-and-bulk-store: each block gathers 64 half-rows (32KB) into SMEM
// with v8 (256-bit) loads, then issues ONE cp.async.bulk 32KB contiguous
// store (TMA path, bypasses L1, large DRAM write bursts).
// Block b covers half-rows [b*64, (b+1)*64): output is perfectly linear.

#define ROWS_PER_BLK 64
#define BLK_BYTES (ROWS_PER_BLK * 512)        // 32 KB
#define GRANULES (ROWS_PER_BLK * 16)           // 32B granules per block = 1024
#define CPT (GRANULES / 256)                   // 4 per thread

struct V8 { unsigned r0,r1,r2,r3,r4,r5,r6,r7; };

__device__ __forceinline__ V8 ldg_v8(const void* p) {
    V8 v;
    asm("ld.global.nc.L2::evict_last.v8.b32 {%0,%1,%2,%3,%4,%5,%6,%7}, [%8];"
        : "=r"(v.r0), "=r"(v.r1), "=r"(v.r2), "=r"(v.r3),
          "=r"(v.r4), "=r"(v.r5), "=r"(v.r6), "=r"(v.r7)
        : "l"(p));
    return v;
}

__device__ __forceinline__ void sts_v8(uint32_t a, const V8& v) {
    asm volatile("st.shared.v4.b32 [%0], {%1,%2,%3,%4};"
        :: "r"(a), "r"(v.r0), "r"(v.r1), "r"(v.r2), "r"(v.r3));
    asm volatile("st.shared.v4.b32 [%0], {%1,%2,%3,%4};"
        :: "r"(a + 16), "r"(v.r4), "r"(v.r5), "r"(v.r6), "r"(v.r7));
}

__global__ void __launch_bounds__(256) link_embed_bulk_kernel(
    const char* __restrict__ Xb,      // byte pointer to X
    const int* __restrict__ idx,      // flat [2E] node ids
    char* __restrict__ outb,          // byte pointer to out
    int H)                            // 2E half-rows
{
    __shared__ __align__(128) char stage[BLK_BYTES];

    const int tid = threadIdx.x;
    const int h0 = blockIdx.x * ROWS_PER_BLK;

    uint32_t smem_base;
    asm("{ .reg .u64 t; cvta.to.shared.u64 t, %1; cvt.u32.u64 %0, t; }"
        : "=r"(smem_base) : "l"(stage));

    if (h0 + ROWS_PER_BLK <= H) {
        // ---- fast path (exact at bench shape) ----
        unsigned off[CPT];
        #pragma unroll
        for (int i = 0; i < CPT; i++) {
            int g = tid + i * 256;                 // granule in block
            int node = __ldg(&idx[h0 + (g >> 4)]); // 16-lane uniform
            off[i] = ((unsigned)node << 9) | ((unsigned)(g & 15) << 5);
        }

        V8 v[CPT];
        #pragma unroll
        for (int i = 0; i < CPT; i++)
            v[i] = ldg_v8(Xb + off[i]);            // 4 gathers in flight

        #pragma unroll
        for (int i = 0; i < CPT; i++)
            sts_v8(smem_base + (unsigned)(tid + i * 256) * 32, v[i]);

        __syncthreads();

        if (tid == 0) {
            asm volatile("fence.proxy.async.shared::cta;" ::: "memory");
            asm volatile(
                "cp.async.bulk.global.shared::cta.bulk_group [%0], [%1], %2;"
                :: "l"(outb + (size_t)h0 * 512), "r"(smem_base), "r"(BLK_BYTES)
                : "memory");
            asm volatile("cp.async.bulk.commit_group;" ::: "memory");
            asm volatile("cp.async.bulk.wait_group 0;" ::: "memory");
        }
    } else {
        // ---- guarded tail (not taken at bench shape): direct stores ----
        for (int g = tid; g < (H - h0) * 16; g += 256) {
            int node = __ldg(&idx[h0 + (g >> 4)]);
            unsigned off = ((unsigned)node << 9) | ((unsigned)(g & 15) << 5);
            V8 v = ldg_v8(Xb + off);
            float4* dst = (float4*)(outb + (size_t)h0 * 512 + (size_t)g * 32);
            float4 a = make_float4(__uint_as_float(v.r0), __uint_as_float(v.r1),
                                   __uint_as_float(v.r2), __uint_as_float(v.r3));
            float4 b = make_float4(__uint_as_float(v.r4), __uint_as_float(v.r5),
                                   __uint_as_float(v.r6), __uint_as_float(v.r7));
            dst[0] = a; dst[1] = b;
        }
    }
}

extern "C" void kernel_launch(void* const* d_in, const int* in_sizes, int n_in,
                              void* d_out, int out_size)
{
    const char* Xb = (const char*)d_in[0];
    const int* idx = (const int*)d_in[1];
    char* outb = (char*)d_out;

    int H = in_sizes[1];                            // 2E half-rows
    int blocks = (H + ROWS_PER_BLK - 1) / ROWS_PER_BLK;
    link_embed_bulk_kernel<<<blocks, 256>>>(Xb, idx, outb, H);
}